// round 9
// baseline (speedup 1.0000x reference)
#include <cuda_runtime.h>
#include <math.h>

#define Bsz 64
#define Tsz 2048
#define Dsz 256
#define Hsz 512
#define Gsz 2048
#define NBREC 256
#define GRP4  64

typedef unsigned long long u64;

// ---- packed fp32x2 helpers (Blackwell FFMA2/FADD2, PTX-only) ----
__device__ __forceinline__ u64 ffma2(u64 a, u64 b, u64 c) {
    u64 d;
    asm("fma.rn.f32x2 %0, %1, %2, %3;" : "=l"(d) : "l"(a), "l"(b), "l"(c));
    return d;
}
__device__ __forceinline__ u64 fadd2(u64 a, u64 b) {
    u64 d;
    asm("add.rn.f32x2 %0, %1, %2;" : "=l"(d) : "l"(a), "l"(b));
    return d;
}
__device__ __forceinline__ u64 dup2(float x) {
    u64 d;
    asm("mov.b64 %0, {%1, %1};" : "=l"(d) : "r"(__float_as_uint(x)));
    return d;
}
__device__ __forceinline__ float lo2(u64 d) { return __int_as_float((int)(unsigned)(d & 0xffffffffu)); }
__device__ __forceinline__ float hi2(u64 d) { return __int_as_float((int)(unsigned)(d >> 32)); }

// Scratch (device globals)
__device__ float g_xw[(size_t)Tsz * Gsz * Bsz];    // [t][col][b]  1 GiB
__device__ float g_Up[64 * Hsz * 32];              // [cg][k][c]   4 MB
__device__ float g_h[2 * Hsz * Bsz];               // [parity][j][b]
__device__ unsigned g_cnt4[128];                   // 4 counters, 128B apart

__global__ void reset_bar_k() { if (threadIdx.x < 128) g_cnt4[threadIdx.x] = 0u; }

// g_Up[cg][k][c] = U[k][gate*512 + cg*8 + jj], c = gate*8 + jj  (32 cols per cg)
__global__ void pack_U_k(const float* __restrict__ U) {
    int idx = blockIdx.x * blockDim.x + threadIdx.x;   // 2^20 total
    int c  = idx & 31;
    int k  = (idx >> 5) & (Hsz - 1);
    int cg = idx >> 14;
    g_Up[idx] = U[k * Gsz + (c >> 3) * Hsz + cg * 8 + (c & 7)];
}

// xW GEMM with FFMA2: C[b][col] = sum_k x[b,t,k]*W[k,col] + bias[col] -> [t][col][b]
__global__ __launch_bounds__(256, 2) void gemm_xw_k(const float* __restrict__ x,
                                                    const float* __restrict__ W,
                                                    const float* __restrict__ bias) {
    const int t   = blockIdx.y;
    const int cb  = blockIdx.x;
    const int tid = threadIdx.x;
    __shared__ float As[32 * 68];
    __shared__ float Bs[32 * 132];
    const int b0 = (tid & 15) * 4;
    const int c0 = (tid >> 4) * 8;

    u64 acc[4][4];
    {
        ulonglong2 bb0 = *(const ulonglong2*)(bias + cb * 128 + c0);
        ulonglong2 bb1 = *(const ulonglong2*)(bias + cb * 128 + c0 + 4);
#pragma unroll
        for (int i = 0; i < 4; ++i) {
            acc[i][0] = bb0.x; acc[i][1] = bb0.y;
            acc[i][2] = bb1.x; acc[i][3] = bb1.y;
        }
    }
    const int arow = tid >> 3;
    const int af4  = tid & 7;
    const int wk   = tid >> 3;
    const int wc   = (tid & 7) * 16;

    for (int k0 = 0; k0 < Dsz; k0 += 32) {
#pragma unroll
        for (int pass = 0; pass < 2; ++pass) {
            int b = arow + pass * 32;
            float4 v = *(const float4*)(x + ((size_t)b * Tsz + t) * Dsz + k0 + af4 * 4);
            As[(af4 * 4 + 0) * 68 + b] = v.x;
            As[(af4 * 4 + 1) * 68 + b] = v.y;
            As[(af4 * 4 + 2) * 68 + b] = v.z;
            As[(af4 * 4 + 3) * 68 + b] = v.w;
        }
        const float* wp = W + (size_t)(k0 + wk) * Gsz + cb * 128 + wc;
        float4 w0 = ((const float4*)wp)[0];
        float4 w1 = ((const float4*)wp)[1];
        float4 w2 = ((const float4*)wp)[2];
        float4 w3 = ((const float4*)wp)[3];
        *(float4*)&Bs[wk * 132 + wc + 0]  = w0;
        *(float4*)&Bs[wk * 132 + wc + 4]  = w1;
        *(float4*)&Bs[wk * 132 + wc + 8]  = w2;
        *(float4*)&Bs[wk * 132 + wc + 12] = w3;
        __syncthreads();
#pragma unroll
        for (int kk = 0; kk < 32; ++kk) {
            float4 a = *(const float4*)&As[kk * 68 + b0];
            ulonglong2 u01 = *(const ulonglong2*)&Bs[kk * 132 + c0];
            ulonglong2 u23 = *(const ulonglong2*)&Bs[kk * 132 + c0 + 4];
            u64 a0 = dup2(a.x), a1 = dup2(a.y), a2 = dup2(a.z), a3 = dup2(a.w);
            acc[0][0] = ffma2(a0, u01.x, acc[0][0]);
            acc[1][0] = ffma2(a1, u01.x, acc[1][0]);
            acc[2][0] = ffma2(a2, u01.x, acc[2][0]);
            acc[3][0] = ffma2(a3, u01.x, acc[3][0]);
            acc[0][1] = ffma2(a0, u01.y, acc[0][1]);
            acc[1][1] = ffma2(a1, u01.y, acc[1][1]);
            acc[2][1] = ffma2(a2, u01.y, acc[2][1]);
            acc[3][1] = ffma2(a3, u01.y, acc[3][1]);
            acc[0][2] = ffma2(a0, u23.x, acc[0][2]);
            acc[1][2] = ffma2(a1, u23.x, acc[1][2]);
            acc[2][2] = ffma2(a2, u23.x, acc[2][2]);
            acc[3][2] = ffma2(a3, u23.x, acc[3][2]);
            acc[0][3] = ffma2(a0, u23.y, acc[0][3]);
            acc[1][3] = ffma2(a1, u23.y, acc[1][3]);
            acc[2][3] = ffma2(a2, u23.y, acc[2][3]);
            acc[3][3] = ffma2(a3, u23.y, acc[3][3]);
        }
        __syncthreads();
    }
#pragma unroll
    for (int jp = 0; jp < 4; ++jp) {
        float4 lo = make_float4(lo2(acc[0][jp]), lo2(acc[1][jp]), lo2(acc[2][jp]), lo2(acc[3][jp]));
        float4 hi = make_float4(hi2(acc[0][jp]), hi2(acc[1][jp]), hi2(acc[2][jp]), hi2(acc[3][jp]));
        size_t base = (size_t)t * Gsz + cb * 128;
        *(float4*)&g_xw[(base + c0 + 2 * jp) * 64 + b0]     = lo;
        *(float4*)&g_xw[(base + c0 + 2 * jp + 1) * 64 + b0] = hi;
    }
}

// ---- per-group barrier: release-REDG arrive + acquire-poll wait ----
__device__ __forceinline__ void garrive(int grp) {
    __syncthreads();
    if (threadIdx.x == 0) {
        asm volatile("red.release.gpu.add.u32 [%0], %1;" :: "l"(&g_cnt4[grp * 32]), "r"(1u) : "memory");
    }
}
__device__ __forceinline__ void gwait(int grp, unsigned target) {
    if (threadIdx.x == 0) {
        unsigned v;
        do {
            asm volatile("ld.acquire.gpu.u32 %0, [%1];" : "=r"(v) : "l"(&g_cnt4[grp * 32]) : "memory");
        } while (v < target);
    }
    __syncthreads();
}

// Persistent recurrence — 4-way batch split, 2 CTAs/SM, independent barrier groups.
// 256 CTAs = (b-quarter bh in 0..3: 16 batches) x (64 col-groups cg: 32 gate cols).
// The two co-resident CTAs belong to different (independent) batch groups, so one
// CTA's barrier/staging glue hides under the other's FFMA2 compute.
// 8 warps; warp w owns k in [64w, 64w+64), staged warp-locally in two 32-row
// halves. Lane tile 4c x 4b (2 pairs): 2 conflict-free LDS + 4 MOV + 8 FFMA2 per k.
// Partials alias the warp's OWN first 32 staging rows (warp-private; written after
// all reads of those rows). Smem: Us[512][32] + hs[8][64][16] + red[32][18] = 98.25KB.
#define REC_SMEM_FLOATS (16384 + 8192 + 32 * 18)

__global__ __launch_bounds__(256, 2) void lstm_rec_k(float* __restrict__ out) {
    extern __shared__ float sm[];
    float* Us  = sm;            // [512][32]
    float* hs  = sm + 16384;    // [w][64][16]; partials alias rows 0..31: [c32][b16]
    float* red = sm + 24576;    // [32][18]

    const int n   = blockIdx.x;
    const int tid = threadIdx.x;
    const int bh  = n & 3;             // batch quarter
    const int cg  = n >> 2;            // 0..63
    const int w   = tid >> 5;
    const int L   = tid & 31;
    const int b0  = (L & 3) * 4;       // batch offset within 16
    const int c0  = (L >> 2) * 4;      // col offset within 32
    const int ub  = tid & 15;          // update role: batch within quarter (tid<128)
    const int ujj = (tid >> 4) & 7;    // update role: hidden-within-cg
    const int jbase = cg * 8;
    const int bb  = bh * 16;           // global batch base

    // resident U slice [512][32]
    {
        const float4* Usrc = (const float4*)(g_Up + (size_t)cg * 16384);
        float4* Udst = (float4*)Us;
        for (int i = tid; i < 4096; i += 256) Udst[i] = Usrc[i];
    }

    // zero h parity 0 (this CTA's 8j x 16b slice)
    if (tid < 128) g_h[(jbase + ujj) * 64 + bb + ub] = 0.0f;
    float creg = 0.0f, hreg = 0.0f;

    unsigned target = GRP4;
    garrive(bh);

    float* hw = hs + w * 1024;         // this warp's staging area [64][16]

    for (int step = 0; step < Tsz; ++step) {
        const int p = step & 1;
        const float* hq = g_h + p * (Hsz * Bsz) + bb;   // row stride 64

        // xW loads in flight across the barrier wait (update-role threads)
        float xg0 = 0.f, xg1 = 0.f, xg2 = 0.f, xg3 = 0.f;
        if (tid < 128) {
            const size_t xbase = (size_t)step * Gsz;
            xg0 = __ldcs(&g_xw[(xbase + 0 * Hsz + jbase + ujj) * 64 + bb + ub]);
            xg1 = __ldcs(&g_xw[(xbase + 1 * Hsz + jbase + ujj) * 64 + bb + ub]);
            xg2 = __ldcs(&g_xw[(xbase + 2 * Hsz + jbase + ujj) * 64 + bb + ub]);
            xg3 = __ldcs(&g_xw[(xbase + 3 * Hsz + jbase + ujj) * 64 + bb + ub]);
        }

        gwait(bh, target);
        target += GRP4;

        u64 acc[8];
#pragma unroll
        for (int j = 0; j < 8; ++j) acc[j] = 0ull;

        // ---- stage half A (rows [64w, 64w+32) x 16 floats) ----
        float4 pv[4];
#pragma unroll
        for (int m = 0; m < 4; ++m) {
            int idx = L + 32 * m; int r = idx >> 2, q = idx & 3;
            pv[m] = __ldcg((const float4*)(hq + (w * 64 + r) * 64) + q);
        }
#pragma unroll
        for (int m = 0; m < 4; ++m) {
            int idx = L + 32 * m; int r = idx >> 2, q = idx & 3;
            *(float4*)&hw[r * 16 + q * 4] = pv[m];
        }
        // LDG for half B in flight under compute A
        float4 pw[4];
#pragma unroll
        for (int m = 0; m < 4; ++m) {
            int idx = L + 32 * m; int r = 32 + (idx >> 2), q = idx & 3;
            pw[m] = __ldcg((const float4*)(hq + (w * 64 + r) * 64) + q);
        }
        __syncwarp();

        // ---- compute half A ----
#pragma unroll 16
        for (int i = 0; i < 32; ++i) {
            ulonglong2 hp = *(const ulonglong2*)&hw[i * 16 + b0];
            float4 uq = *(const float4*)&Us[(w * 64 + i) * 32 + c0];
            u64 u0 = dup2(uq.x), u1 = dup2(uq.y), u2 = dup2(uq.z), u3 = dup2(uq.w);
            acc[0] = ffma2(hp.x, u0, acc[0]);
            acc[1] = ffma2(hp.y, u0, acc[1]);
            acc[2] = ffma2(hp.x, u1, acc[2]);
            acc[3] = ffma2(hp.y, u1, acc[3]);
            acc[4] = ffma2(hp.x, u2, acc[4]);
            acc[5] = ffma2(hp.y, u2, acc[5]);
            acc[6] = ffma2(hp.x, u3, acc[6]);
            acc[7] = ffma2(hp.y, u3, acc[7]);
        }

        // ---- stage half B ----
#pragma unroll
        for (int m = 0; m < 4; ++m) {
            int idx = L + 32 * m; int r = 32 + (idx >> 2), q = idx & 3;
            *(float4*)&hw[r * 16 + q * 4] = pw[m];
        }
        __syncwarp();

        // ---- compute half B ----
#pragma unroll 16
        for (int i = 32; i < 64; ++i) {
            ulonglong2 hp = *(const ulonglong2*)&hw[i * 16 + b0];
            float4 uq = *(const float4*)&Us[(w * 64 + i) * 32 + c0];
            u64 u0 = dup2(uq.x), u1 = dup2(uq.y), u2 = dup2(uq.z), u3 = dup2(uq.w);
            acc[0] = ffma2(hp.x, u0, acc[0]);
            acc[1] = ffma2(hp.y, u0, acc[1]);
            acc[2] = ffma2(hp.x, u1, acc[2]);
            acc[3] = ffma2(hp.y, u1, acc[3]);
            acc[4] = ffma2(hp.x, u2, acc[4]);
            acc[5] = ffma2(hp.y, u2, acc[5]);
            acc[6] = ffma2(hp.x, u3, acc[6]);
            acc[7] = ffma2(hp.y, u3, acc[7]);
        }
        __syncwarp();   // order this warp's hw reads before aliasing writes

        // per-warp partial tile [32c][16b] into rows 0..31 of own staging area
#pragma unroll
        for (int j = 0; j < 4; ++j)
            *(ulonglong2*)&hw[(c0 + j) * 16 + b0] =
                make_ulonglong2(acc[2 * j], acc[2 * j + 1]);
        __syncthreads();

        // reduce over 8 warps: thread -> col rc = tid>>3, b-pair rq = (tid&7)*2
        {
            const int rc = tid >> 3, rq = (tid & 7) * 2;
            u64 s = *(const u64*)&hs[rc * 16 + rq];
#pragma unroll
            for (int ww = 1; ww < 8; ++ww)
                s = fadd2(s, *(const u64*)&hs[ww * 1024 + rc * 16 + rq]);
            *(u64*)&red[rc * 18 + rq] = s;
        }
        __syncthreads();

        // elementwise update: tid<128 owns (b = bb+ub, j = jbase+ujj)
        if (tid < 128) {
            float v0 = red[(0 * 8 + ujj) * 18 + ub] + xg0;
            float v1 = red[(1 * 8 + ujj) * 18 + ub] + xg1;
            float v2 = red[(2 * 8 + ujj) * 18 + ub] + xg2;
            float v3 = red[(3 * 8 + ujj) * 18 + ub] + xg3;
            float ig = 1.0f / (1.0f + __expf(-v0));
            float fg = 1.0f / (1.0f + __expf(-v1));
            float gg = tanhf(v2);
            float og = 1.0f / (1.0f + __expf(-v3));
            creg = fg * creg + ig * gg;
            hreg = og * tanhf(creg);
            __stcg(&g_h[(p ^ 1) * (Hsz * Bsz) + (jbase + ujj) * 64 + bb + ub], hreg);
        }

        garrive(bh);
    }

    if (tid < 128) {
        out[(bb + ub) * Hsz + jbase + ujj] = hreg;
        out[Bsz * Hsz + (bb + ub) * Hsz + jbase + ujj] = creg;
    }
}

extern "C" void kernel_launch(void* const* d_in, const int* in_sizes, int n_in,
                              void* d_out, int out_size) {
    const float* x    = (const float*)d_in[0];
    const float* W    = (const float*)d_in[1];
    const float* U    = (const float*)d_in[2];
    const float* bias = (const float*)d_in[3];
    float* out = (float*)d_out;
    (void)in_sizes; (void)n_in; (void)out_size;

    static int smem_set = 0;
    if (!smem_set) {
        cudaFuncSetAttribute(lstm_rec_k, cudaFuncAttributeMaxDynamicSharedMemorySize,
                             REC_SMEM_FLOATS * 4);
        smem_set = 1;
    }

    pack_U_k<<<2048, 512>>>(U);
    dim3 g(16, Tsz);
    gemm_xw_k<<<g, 256>>>(x, W, bias);
    reset_bar_k<<<1, 128>>>();
    lstm_rec_k<<<NBREC, 256, REC_SMEM_FLOATS * 4>>>(out);
}

// round 10
// speedup vs baseline: 1.0801x; 1.0801x over previous
#include <cuda_runtime.h>
#include <math.h>

#define Bsz 64
#define Tsz 2048
#define Dsz 256
#define Hsz 512
#define Gsz 2048
#define NB  128

typedef unsigned long long u64;

// ---- packed fp32x2 helpers (Blackwell FFMA2/FADD2, PTX-only) ----
__device__ __forceinline__ u64 ffma2(u64 a, u64 b, u64 c) {
    u64 d;
    asm("fma.rn.f32x2 %0, %1, %2, %3;" : "=l"(d) : "l"(a), "l"(b), "l"(c));
    return d;
}
__device__ __forceinline__ u64 fadd2(u64 a, u64 b) {
    u64 d;
    asm("add.rn.f32x2 %0, %1, %2;" : "=l"(d) : "l"(a), "l"(b));
    return d;
}
__device__ __forceinline__ u64 dup2(float x) {
    u64 d;
    asm("mov.b64 %0, {%1, %1};" : "=l"(d) : "r"(__float_as_uint(x)));
    return d;
}
__device__ __forceinline__ float lo2(u64 d) { return __int_as_float((int)(unsigned)(d & 0xffffffffu)); }
__device__ __forceinline__ float hi2(u64 d) { return __int_as_float((int)(unsigned)(d >> 32)); }

// Scratch (device globals)
__device__ float g_xw[(size_t)Tsz * Gsz * Bsz];    // [t][col][b]  1 GiB
__device__ float g_Up[64 * Hsz * 32];              // [cg][k][c]   4 MB
__device__ float g_h[2 * Hsz * Bsz];               // [parity][j][b]
__device__ unsigned g_cnt;                         // single arrival counter

__global__ void reset_bar_k() { g_cnt = 0u; }

// g_Up[cg][k][c] = U[k][gate*512 + cg*8 + jj], c = gate*8 + jj  (32 cols per cg)
__global__ void pack_U_k(const float* __restrict__ U) {
    int idx = blockIdx.x * blockDim.x + threadIdx.x;   // 2^20 total
    int c  = idx & 31;
    int k  = (idx >> 5) & (Hsz - 1);
    int cg = idx >> 14;
    g_Up[idx] = U[k * Gsz + (c >> 3) * Hsz + cg * 8 + (c & 7)];
}

// xW GEMM with FFMA2: C[b][col] = sum_k x[b,t,k]*W[k,col] + bias[col] -> [t][col][b]
__global__ __launch_bounds__(256, 2) void gemm_xw_k(const float* __restrict__ x,
                                                    const float* __restrict__ W,
                                                    const float* __restrict__ bias) {
    const int t   = blockIdx.y;
    const int cb  = blockIdx.x;
    const int tid = threadIdx.x;
    __shared__ float As[32 * 68];
    __shared__ float Bs[32 * 132];
    const int b0 = (tid & 15) * 4;
    const int c0 = (tid >> 4) * 8;

    u64 acc[4][4];
    {
        ulonglong2 bb0 = *(const ulonglong2*)(bias + cb * 128 + c0);
        ulonglong2 bb1 = *(const ulonglong2*)(bias + cb * 128 + c0 + 4);
#pragma unroll
        for (int i = 0; i < 4; ++i) {
            acc[i][0] = bb0.x; acc[i][1] = bb0.y;
            acc[i][2] = bb1.x; acc[i][3] = bb1.y;
        }
    }
    const int arow = tid >> 3;
    const int af4  = tid & 7;
    const int wk   = tid >> 3;
    const int wc   = (tid & 7) * 16;

    for (int k0 = 0; k0 < Dsz; k0 += 32) {
#pragma unroll
        for (int pass = 0; pass < 2; ++pass) {
            int b = arow + pass * 32;
            float4 v = *(const float4*)(x + ((size_t)b * Tsz + t) * Dsz + k0 + af4 * 4);
            As[(af4 * 4 + 0) * 68 + b] = v.x;
            As[(af4 * 4 + 1) * 68 + b] = v.y;
            As[(af4 * 4 + 2) * 68 + b] = v.z;
            As[(af4 * 4 + 3) * 68 + b] = v.w;
        }
        const float* wp = W + (size_t)(k0 + wk) * Gsz + cb * 128 + wc;
        float4 w0 = ((const float4*)wp)[0];
        float4 w1 = ((const float4*)wp)[1];
        float4 w2 = ((const float4*)wp)[2];
        float4 w3 = ((const float4*)wp)[3];
        *(float4*)&Bs[wk * 132 + wc + 0]  = w0;
        *(float4*)&Bs[wk * 132 + wc + 4]  = w1;
        *(float4*)&Bs[wk * 132 + wc + 8]  = w2;
        *(float4*)&Bs[wk * 132 + wc + 12] = w3;
        __syncthreads();
#pragma unroll
        for (int kk = 0; kk < 32; ++kk) {
            float4 a = *(const float4*)&As[kk * 68 + b0];
            ulonglong2 u01 = *(const ulonglong2*)&Bs[kk * 132 + c0];
            ulonglong2 u23 = *(const ulonglong2*)&Bs[kk * 132 + c0 + 4];
            u64 a0 = dup2(a.x), a1 = dup2(a.y), a2 = dup2(a.z), a3 = dup2(a.w);
            acc[0][0] = ffma2(a0, u01.x, acc[0][0]);
            acc[1][0] = ffma2(a1, u01.x, acc[1][0]);
            acc[2][0] = ffma2(a2, u01.x, acc[2][0]);
            acc[3][0] = ffma2(a3, u01.x, acc[3][0]);
            acc[0][1] = ffma2(a0, u01.y, acc[0][1]);
            acc[1][1] = ffma2(a1, u01.y, acc[1][1]);
            acc[2][1] = ffma2(a2, u01.y, acc[2][1]);
            acc[3][1] = ffma2(a3, u01.y, acc[3][1]);
            acc[0][2] = ffma2(a0, u23.x, acc[0][2]);
            acc[1][2] = ffma2(a1, u23.x, acc[1][2]);
            acc[2][2] = ffma2(a2, u23.x, acc[2][2]);
            acc[3][2] = ffma2(a3, u23.x, acc[3][2]);
            acc[0][3] = ffma2(a0, u23.y, acc[0][3]);
            acc[1][3] = ffma2(a1, u23.y, acc[1][3]);
            acc[2][3] = ffma2(a2, u23.y, acc[2][3]);
            acc[3][3] = ffma2(a3, u23.y, acc[3][3]);
        }
        __syncthreads();
    }
#pragma unroll
    for (int jp = 0; jp < 4; ++jp) {
        float4 lo = make_float4(lo2(acc[0][jp]), lo2(acc[1][jp]), lo2(acc[2][jp]), lo2(acc[3][jp]));
        float4 hi = make_float4(hi2(acc[0][jp]), hi2(acc[1][jp]), hi2(acc[2][jp]), hi2(acc[3][jp]));
        size_t base = (size_t)t * Gsz + cb * 128;
        *(float4*)&g_xw[(base + c0 + 2 * jp) * 64 + b0]     = lo;
        *(float4*)&g_xw[(base + c0 + 2 * jp + 1) * 64 + b0] = hi;
    }
}

// ---- chip barrier: release-REDG arrive + acquire-poll wait (no MEMBAR) ----
__device__ __forceinline__ void garrive_all() {
    __syncthreads();
    if (threadIdx.x == 0) {
        asm volatile("red.release.gpu.add.u32 [%0], %1;" :: "l"(&g_cnt), "r"(1u) : "memory");
    }
}
__device__ __forceinline__ void gwait_all(unsigned target) {
    if (threadIdx.x == 0) {
        unsigned v;
        do {
            asm volatile("ld.acquire.gpu.u32 %0, [%1];" : "=r"(v) : "l"(&g_cnt) : "memory");
        } while (v < target);
    }
    __syncthreads();
}

// Persistent recurrence — R7 skeleton + crossbar-minimal compute.
// 128 CTAs = (b-half bh) x (64 col-groups cg: 8 hidden units = 32 gate cols).
// 8 warps; warp w owns k in [64w, 64w+64). k-PAIRED lanes: kg2 = L>>4 picks
// even/odd k row; lane tile 8b x 8c (t = L&15: b0=(t&3)*8, c0=(t>>2)*8).
// Per k-pair: 4 LDS.128 (h x2, U x2), each exactly 128B distinct, conflict-free
// thanks to 36-float row padding. 32 FFMA2 per lane per iter.
// After compute: SHFL-XOR(16) merges the two k-group partials inside each warp;
// cross-warp reduce stays 8-way. Staging: double-halved warp-local (R7).
// Smem: Us[512][36] + hs[8][64][36] + part[8][32][32] + red[32][36] = 180.5KB.
#define REC_SMEM_FLOATS (18432 + 18432 + 8192 + 1152)

__global__ __launch_bounds__(256, 1) void lstm_rec_k(float* __restrict__ out) {
    extern __shared__ float sm[];
    float* Us   = sm;            // [512][36]
    float* hs   = sm + 18432;    // [w][64][36]
    float* part = sm + 36864;    // [w][32c][32b]
    float* red  = sm + 45056;    // [32][36]

    const int n   = blockIdx.x;
    const int tid = threadIdx.x;
    const int bh  = n & 1;
    const int cg  = n >> 1;
    const int w   = tid >> 5;
    const int L   = tid & 31;
    const int kg2 = L >> 4;            // k parity within pair
    const int t16 = L & 15;
    const int b0  = (t16 & 3) * 8;     // 0,8,16,24
    const int c0  = (t16 >> 2) * 8;    // 0,8,16,24
    const int ub  = tid & 31;          // update role: batch within half
    const int ujj = tid >> 5;          // update role: hidden-within-cg 0..7
    const int jbase = cg * 8;

    // resident U slice [512][36] (padded rows)
    for (int i = tid; i < 4096; i += 256) {
        int k = i >> 3, q = i & 7;
        *(float4*)&Us[k * 36 + q * 4] = *(const float4*)&g_Up[(size_t)cg * 16384 + k * 32 + q * 4];
    }

    // zero h parity 0 (this CTA's slice)
    g_h[(jbase + ujj) * 64 + bh * 32 + ub] = 0.0f;
    float creg = 0.0f, hreg = 0.0f;

    unsigned target = NB;
    garrive_all();

    float* hw = hs + w * 2304;              // this warp's staging area [64][36]
    const float* Uw = Us + (w * 64) * 36;   // this warp's U rows

    for (int step = 0; step < Tsz; ++step) {
        const int p = step & 1;
        const float* hq = g_h + p * (Hsz * Bsz) + bh * 32;   // row stride 64

        // xW loads in flight across the barrier wait
        const size_t xbase = (size_t)step * Gsz;
        float xg0 = __ldcs(&g_xw[(xbase + 0 * Hsz + jbase + ujj) * 64 + bh * 32 + ub]);
        float xg1 = __ldcs(&g_xw[(xbase + 1 * Hsz + jbase + ujj) * 64 + bh * 32 + ub]);
        float xg2 = __ldcs(&g_xw[(xbase + 2 * Hsz + jbase + ujj) * 64 + bh * 32 + ub]);
        float xg3 = __ldcs(&g_xw[(xbase + 3 * Hsz + jbase + ujj) * 64 + bh * 32 + ub]);

        gwait_all(target);
        target += NB;

        u64 acc[8][4];                      // [c][b-pair]
#pragma unroll
        for (int j = 0; j < 8; ++j)
#pragma unroll
            for (int i = 0; i < 4; ++i) acc[j][i] = 0ull;

        // ---- stage half A (rows [0,32) of warp slice) ----
        float4 pv[8];
#pragma unroll
        for (int m = 0; m < 8; ++m) {
            int idx = L + 32 * m; int r = idx >> 3, q = idx & 7;
            pv[m] = __ldcg((const float4*)(hq + (w * 64 + r) * 64) + q);
        }
#pragma unroll
        for (int m = 0; m < 8; ++m) {
            int idx = L + 32 * m; int r = idx >> 3, q = idx & 7;
            *(float4*)&hw[r * 36 + q * 4] = pv[m];
        }
        // LDG for half B in flight under compute A
        float4 pw[8];
#pragma unroll
        for (int m = 0; m < 8; ++m) {
            int idx = L + 32 * m; int r = 32 + (idx >> 3), q = idx & 7;
            pw[m] = __ldcg((const float4*)(hq + (w * 64 + r) * 64) + q);
        }
        __syncwarp();

        // ---- compute half A: k-pairs over rows [0,32) ----
#pragma unroll 8
        for (int i = 0; i < 16; ++i) {
            const int row = 2 * i + kg2;
            const float* hr = hw + row * 36;
            const float* ur = Uw + row * 36;
            ulonglong2 hA = *(const ulonglong2*)&hr[b0];
            ulonglong2 hB = *(const ulonglong2*)&hr[b0 + 4];
            float4 uA = *(const float4*)&ur[c0];
            float4 uB = *(const float4*)&ur[c0 + 4];
            u64 ud;
            ud = dup2(uA.x);
            acc[0][0] = ffma2(hA.x, ud, acc[0][0]); acc[0][1] = ffma2(hA.y, ud, acc[0][1]);
            acc[0][2] = ffma2(hB.x, ud, acc[0][2]); acc[0][3] = ffma2(hB.y, ud, acc[0][3]);
            ud = dup2(uA.y);
            acc[1][0] = ffma2(hA.x, ud, acc[1][0]); acc[1][1] = ffma2(hA.y, ud, acc[1][1]);
            acc[1][2] = ffma2(hB.x, ud, acc[1][2]); acc[1][3] = ffma2(hB.y, ud, acc[1][3]);
            ud = dup2(uA.z);
            acc[2][0] = ffma2(hA.x, ud, acc[2][0]); acc[2][1] = ffma2(hA.y, ud, acc[2][1]);
            acc[2][2] = ffma2(hB.x, ud, acc[2][2]); acc[2][3] = ffma2(hB.y, ud, acc[2][3]);
            ud = dup2(uA.w);
            acc[3][0] = ffma2(hA.x, ud, acc[3][0]); acc[3][1] = ffma2(hA.y, ud, acc[3][1]);
            acc[3][2] = ffma2(hB.x, ud, acc[3][2]); acc[3][3] = ffma2(hB.y, ud, acc[3][3]);
            ud = dup2(uB.x);
            acc[4][0] = ffma2(hA.x, ud, acc[4][0]); acc[4][1] = ffma2(hA.y, ud, acc[4][1]);
            acc[4][2] = ffma2(hB.x, ud, acc[4][2]); acc[4][3] = ffma2(hB.y, ud, acc[4][3]);
            ud = dup2(uB.y);
            acc[5][0] = ffma2(hA.x, ud, acc[5][0]); acc[5][1] = ffma2(hA.y, ud, acc[5][1]);
            acc[5][2] = ffma2(hB.x, ud, acc[5][2]); acc[5][3] = ffma2(hB.y, ud, acc[5][3]);
            ud = dup2(uB.z);
            acc[6][0] = ffma2(hA.x, ud, acc[6][0]); acc[6][1] = ffma2(hA.y, ud, acc[6][1]);
            acc[6][2] = ffma2(hB.x, ud, acc[6][2]); acc[6][3] = ffma2(hB.y, ud, acc[6][3]);
            ud = dup2(uB.w);
            acc[7][0] = ffma2(hA.x, ud, acc[7][0]); acc[7][1] = ffma2(hA.y, ud, acc[7][1]);
            acc[7][2] = ffma2(hB.x, ud, acc[7][2]); acc[7][3] = ffma2(hB.y, ud, acc[7][3]);
        }

        // ---- stage half B ----
#pragma unroll
        for (int m = 0; m < 8; ++m) {
            int idx = L + 32 * m; int r = 32 + (idx >> 3), q = idx & 7;
            *(float4*)&hw[r * 36 + q * 4] = pw[m];
        }
        __syncwarp();

        // ---- compute half B: k-pairs over rows [32,64) ----
#pragma unroll 8
        for (int i = 16; i < 32; ++i) {
            const int row = 2 * i + kg2;
            const float* hr = hw + row * 36;
            const float* ur = Uw + row * 36;
            ulonglong2 hA = *(const ulonglong2*)&hr[b0];
            ulonglong2 hB = *(const ulonglong2*)&hr[b0 + 4];
            float4 uA = *(const float4*)&ur[c0];
            float4 uB = *(const float4*)&ur[c0 + 4];
            u64 ud;
            ud = dup2(uA.x);
            acc[0][0] = ffma2(hA.x, ud, acc[0][0]); acc[0][1] = ffma2(hA.y, ud, acc[0][1]);
            acc[0][2] = ffma2(hB.x, ud, acc[0][2]); acc[0][3] = ffma2(hB.y, ud, acc[0][3]);
            ud = dup2(uA.y);
            acc[1][0] = ffma2(hA.x, ud, acc[1][0]); acc[1][1] = ffma2(hA.y, ud, acc[1][1]);
            acc[1][2] = ffma2(hB.x, ud, acc[1][2]); acc[1][3] = ffma2(hB.y, ud, acc[1][3]);
            ud = dup2(uA.z);
            acc[2][0] = ffma2(hA.x, ud, acc[2][0]); acc[2][1] = ffma2(hA.y, ud, acc[2][1]);
            acc[2][2] = ffma2(hB.x, ud, acc[2][2]); acc[2][3] = ffma2(hB.y, ud, acc[2][3]);
            ud = dup2(uA.w);
            acc[3][0] = ffma2(hA.x, ud, acc[3][0]); acc[3][1] = ffma2(hA.y, ud, acc[3][1]);
            acc[3][2] = ffma2(hB.x, ud, acc[3][2]); acc[3][3] = ffma2(hB.y, ud, acc[3][3]);
            ud = dup2(uB.x);
            acc[4][0] = ffma2(hA.x, ud, acc[4][0]); acc[4][1] = ffma2(hA.y, ud, acc[4][1]);
            acc[4][2] = ffma2(hB.x, ud, acc[4][2]); acc[4][3] = ffma2(hB.y, ud, acc[4][3]);
            ud = dup2(uB.y);
            acc[5][0] = ffma2(hA.x, ud, acc[5][0]); acc[5][1] = ffma2(hA.y, ud, acc[5][1]);
            acc[5][2] = ffma2(hB.x, ud, acc[5][2]); acc[5][3] = ffma2(hB.y, ud, acc[5][3]);
            ud = dup2(uB.z);
            acc[6][0] = ffma2(hA.x, ud, acc[6][0]); acc[6][1] = ffma2(hA.y, ud, acc[6][1]);
            acc[6][2] = ffma2(hB.x, ud, acc[6][2]); acc[6][3] = ffma2(hB.y, ud, acc[6][3]);
            ud = dup2(uB.w);
            acc[7][0] = ffma2(hA.x, ud, acc[7][0]); acc[7][1] = ffma2(hA.y, ud, acc[7][1]);
            acc[7][2] = ffma2(hB.x, ud, acc[7][2]); acc[7][3] = ffma2(hB.y, ud, acc[7][3]);
        }

        // ---- merge the two k-groups inside the warp (SHFL path, not crossbar) ----
#pragma unroll
        for (int j = 0; j < 8; ++j)
#pragma unroll
            for (int i = 0; i < 4; ++i)
                acc[j][i] = fadd2(acc[j][i], __shfl_xor_sync(0xffffffffu, acc[j][i], 16));

        // per-warp partial tile [32c][32b]; lanes 0-15 hold the merged sums
        if (kg2 == 0) {
#pragma unroll
            for (int j = 0; j < 8; ++j) {
                float* pp = part + w * 1024 + (c0 + j) * 32 + b0;
                *(ulonglong2*)pp       = make_ulonglong2(acc[j][0], acc[j][1]);
                *(ulonglong2*)(pp + 4) = make_ulonglong2(acc[j][2], acc[j][3]);
            }
        }
        __syncthreads();

        // reduce over 8 warps: thread -> col rc = tid>>3, b-quad rq = (tid&7)*4
        {
            const int rc = tid >> 3, rq = (tid & 7) * 4;
            ulonglong2 s = *(const ulonglong2*)&part[rc * 32 + rq];
#pragma unroll
            for (int ww = 1; ww < 8; ++ww) {
                ulonglong2 v = *(const ulonglong2*)&part[ww * 1024 + rc * 32 + rq];
                s.x = fadd2(s.x, v.x);
                s.y = fadd2(s.y, v.y);
            }
            *(ulonglong2*)&red[rc * 36 + rq] = s;
        }
        __syncthreads();

        // elementwise update: thread owns (b = ub, j = jbase + ujj)
        float v0 = red[(0 * 8 + ujj) * 36 + ub] + xg0;
        float v1 = red[(1 * 8 + ujj) * 36 + ub] + xg1;
        float v2 = red[(2 * 8 + ujj) * 36 + ub] + xg2;
        float v3 = red[(3 * 8 + ujj) * 36 + ub] + xg3;
        float ig = 1.0f / (1.0f + __expf(-v0));
        float fg = 1.0f / (1.0f + __expf(-v1));
        float gg = tanhf(v2);
        float og = 1.0f / (1.0f + __expf(-v3));
        creg = fg * creg + ig * gg;
        hreg = og * tanhf(creg);
        __stcg(&g_h[(p ^ 1) * (Hsz * Bsz) + (jbase + ujj) * 64 + bh * 32 + ub], hreg);

        garrive_all();
    }

    out[(bh * 32 + ub) * Hsz + jbase + ujj] = hreg;
    out[Bsz * Hsz + (bh * 32 + ub) * Hsz + jbase + ujj] = creg;
}

extern "C" void kernel_launch(void* const* d_in, const int* in_sizes, int n_in,
                              void* d_out, int out_size) {
    const float* x    = (const float*)d_in[0];
    const float* W    = (const float*)d_in[1];
    const float* U    = (const float*)d_in[2];
    const float* bias = (const float*)d_in[3];
    float* out = (float*)d_out;
    (void)in_sizes; (void)n_in; (void)out_size;

    static int smem_set = 0;
    if (!smem_set) {
        cudaFuncSetAttribute(lstm_rec_k, cudaFuncAttributeMaxDynamicSharedMemorySize,
                             REC_SMEM_FLOATS * 4);
        smem_set = 1;
    }

    pack_U_k<<<2048, 512>>>(U);
    dim3 g(16, Tsz);
    gemm_xw_k<<<g, 256>>>(x, W, bias);
    reset_bar_k<<<1, 1>>>();
    lstm_rec_k<<<NB, 256, REC_SMEM_FLOATS * 4>>>(out);
}